// round 15
// baseline (speedup 1.0000x reference)
#include <cuda_runtime.h>
#include <cuda_fp16.h>
#include <cstdint>

#define BATCH 2
#define CH    64
#define DD    20
#define NN    8000

// Projections in fp16. g_Q,g_K: [b][n][c] with channel-words permuted for LDS.128 frags.
// g_V: [b][c][n] with key-words permuted within each 64-block.
__device__ __align__(256) __half g_Qh[BATCH * NN * CH];
__device__ __align__(256) __half g_Kh[BATCH * NN * CH];
__device__ __align__(256) __half g_Vh[BATCH * NN * CH];

#define FMA2(d, a, b_) \
    asm("fma.rn.f32x2 %0, %1, %2, %0;" : "+l"(d) : "l"(a), "l"(b_))

// ---------------------------------------------------------------------------
// Conv kernel v2: 128-n tiles, 256 threads, double-buffered staging (ONE
// barrier per k-chunk), f32x2 inner loop, smem-transposed coalesced output.
// ---------------------------------------------------------------------------
__global__ __launch_bounds__(256) void conv_kernel(
    const float* __restrict__ x,
    const float* __restrict__ qw, const float* __restrict__ qb,
    const float* __restrict__ kw, const float* __restrict__ kbias,
    const float* __restrict__ vw, const float* __restrict__ vb)
{
    const int nt = blockIdx.x, b = blockIdx.y, cv = blockIdx.z;
    const float* Wp = (cv == 0) ? qw : ((cv == 1) ? kw : vw);
    const float* Bp = (cv == 0) ? qb : ((cv == 1) ? kbias : vb);
    const int n0 = (nt < 62) ? nt * 128 : (NN - 128);   // 64-aligned; last tile overlaps
    const int tid = threadIdx.x;

    __shared__ float Ws[2][16][68];
    __shared__ float Xs[2][16][132];
    __shared__ __align__(16) __half Os[8704];   // QK: [128][68]; V: [64][136]

    const int tn = (tid & 31) * 4;   // 4 n columns (16B aligned)
    const int tc = (tid >> 5) * 8;   // 8 output channels = 4 pairs

    uint64_t acc2[4][4];
#pragma unroll
    for (int ip = 0; ip < 4; ip++)
#pragma unroll
        for (int j = 0; j < 4; j++) acc2[ip][j] = 0ull;

    // staging assignment: thread stages 8 n of one k-row per chunk
    const int ks = tid >> 4;          // k row 0..15
    const int nb = (tid & 15) * 8;    // n base 0..120
    int pd[8], ph[8], pw[8];
#pragma unroll
    for (int j = 0; j < 8; j++) {
        int n = n0 + nb + j;
        pd[j] = n / 400;
        int rem = n - pd[j] * 400;
        ph[j] = rem / 20;
        pw[j] = rem - ph[j] * 20;
    }

    // one-chunk staging (weights + im2col X) into buffer bf
    auto stage = [&](int k0, int bf) {
        {   // weights: 64co x 16k words = 256 float4, one per thread
            int co = tid >> 2, k4 = (tid & 3) * 4;
            float4 wv = *reinterpret_cast<const float4*>(Wp + co * 192 + k0 + k4);
            Ws[bf][k4 + 0][co] = wv.x; Ws[bf][k4 + 1][co] = wv.y;
            Ws[bf][k4 + 2][co] = wv.z; Ws[bf][k4 + 3][co] = wv.w;
        }
        {
            int kk = k0 + ks;
            int ci = kk / 3;
            int dt = kk - ci * 3 - 1;
#pragma unroll
            for (int j = 0; j < 8; j++) {
                int d = pd[j], h = ph[j], w = pw[j];
                if (cv == 0) h += dt; else if (cv == 1) d += dt; else w += dt;
                unsigned cd = (cv == 0) ? (unsigned)h : ((cv == 1) ? (unsigned)d : (unsigned)w);
                float val = 0.f;
                if (cd < 20u)
                    val = x[((b * CH + ci) * DD + d) * 400 + h * 20 + w];
                Xs[bf][ks][nb + j] = val;
            }
        }
    };

    stage(0, 0);
    __syncthreads();

    for (int c = 0; c < 12; c++) {
        if (c + 1 < 12) stage((c + 1) * 16, (c + 1) & 1);   // overlaps compute below
        const int bf = c & 1;
#pragma unroll
        for (int kk = 0; kk < 16; kk++) {
            float4 xr = *reinterpret_cast<const float4*>(&Xs[bf][kk][tn]);
            const uint64_t* wp = reinterpret_cast<const uint64_t*>(&Ws[bf][kk][tc]);
            uint64_t w2[4];
            w2[0] = wp[0]; w2[1] = wp[1]; w2[2] = wp[2]; w2[3] = wp[3];
            uint64_t xb[4];
            asm("mov.b64 %0, {%1,%1};" : "=l"(xb[0]) : "f"(xr.x));
            asm("mov.b64 %0, {%1,%1};" : "=l"(xb[1]) : "f"(xr.y));
            asm("mov.b64 %0, {%1,%1};" : "=l"(xb[2]) : "f"(xr.z));
            asm("mov.b64 %0, {%1,%1};" : "=l"(xb[3]) : "f"(xr.w));
#pragma unroll
            for (int ip = 0; ip < 4; ip++) {
                FMA2(acc2[ip][0], w2[ip], xb[0]);
                FMA2(acc2[ip][1], w2[ip], xb[1]);
                FMA2(acc2[ip][2], w2[ip], xb[2]);
                FMA2(acc2[ip][3], w2[ip], xb[3]);
            }
        }
        __syncthreads();   // staged c+1 visible; buffer (c&1) free for restage at c+2
    }

    // ---- stage results in smem (fp16), natural layout ----
#pragma unroll
    for (int ip = 0; ip < 4; ip++) {
        float lo[4], hi[4];
#pragma unroll
        for (int j = 0; j < 4; j++)
            asm("mov.b64 {%0,%1}, %2;" : "=f"(lo[j]), "=f"(hi[j]) : "l"(acc2[ip][j]));
#pragma unroll
        for (int half = 0; half < 2; half++) {
            const int co = tc + 2 * ip + half;
            const float bias = Bp[co];
#pragma unroll
            for (int j = 0; j < 4; j++) {
                const int nl = tn + j;
                const __half hv = __float2half_rn((half ? hi[j] : lo[j]) + bias);
                if (cv == 2) Os[co * 136 + nl] = hv;   // V: [channel][n]
                else         Os[nl * 68 + co] = hv;    // Q/K: [n][channel]
            }
        }
    }
    __syncthreads();

    // ---- coalesced output with word permutation applied at the smem gather ----
    if (cv == 2) {
        // V: 64 rows (channels) x 64 words; perm per 32-word (64-n) block
        const int R = tid >> 2, part = tid & 3;
        const uint32_t* Osw = reinterpret_cast<const uint32_t*>(&Os[R * 136]);
        __half* dst = g_Vh + ((size_t)(b * CH + R)) * NN + n0;
        uint32_t wbuf[16];
#pragma unroll
        for (int idx = 0; idx < 16; idx++) {
            const int p = part * 16 + idx;
            const int b2 = p >> 5, pin = p & 31;
            const int k16 = ((pin >> 4) << 1) | (pin & 1);
            const int jj = (((pin >> 1) & 1) << 2) | ((pin >> 2) & 3);
            wbuf[idx] = Osw[b2 * 32 + k16 * 8 + jj];
        }
        uint4* d4 = reinterpret_cast<uint4*>(dst) + part * 4;
#pragma unroll
        for (int c = 0; c < 4; c++)
            d4[c] = make_uint4(wbuf[4 * c], wbuf[4 * c + 1], wbuf[4 * c + 2], wbuf[4 * c + 3]);
    } else {
        // Q/K: 128 rows (n) x 32 words; perm on the 32 channel-words
        const int R = tid >> 1, h4 = tid & 1;
        const uint32_t* Osw = reinterpret_cast<const uint32_t*>(&Os[R * 68]);
        __half* dst = (cv ? g_Kh : g_Qh) + ((size_t)(b * NN + n0 + R)) * CH;
        uint32_t wbuf[16];
#pragma unroll
        for (int idx = 0; idx < 16; idx++) {
            const int p = h4 * 16 + idx;
            const int k16 = ((p >> 4) << 1) | (p & 1);
            const int jj = (((p >> 1) & 1) << 2) | ((p >> 2) & 3);
            wbuf[idx] = Osw[k16 * 8 + jj];
        }
        uint4* d4 = reinterpret_cast<uint4*>(dst) + h4 * 4;
#pragma unroll
        for (int c = 0; c < 4; c++)
            d4[c] = make_uint4(wbuf[4 * c], wbuf[4 * c + 1], wbuf[4 * c + 2], wbuf[4 * c + 3]);
    }
}

// ---------------------------------------------------------------------------
// Attention kernel (unchanged from R14): m32 per warp, 256 threads, 1 CTA/SM,
// two key-split groups, 6-stage ring, one barrier per tile, kp-split body.
// ---------------------------------------------------------------------------
__device__ __forceinline__ uint32_t smem_u32(const void* p) {
    uint32_t a;
    asm("{ .reg .u64 t; cvta.to.shared.u64 t, %1; cvt.u32.u64 %0, t; }" : "=r"(a) : "l"(p));
    return a;
}

#define MMA16(d, a, b0_, b1_)                                                 \
    asm volatile("mma.sync.aligned.m16n8k16.row.col.f32.f16.f16.f32 "         \
                 "{%0,%1,%2,%3},{%4,%5,%6,%7},{%8,%9},{%0,%1,%2,%3};"         \
                 : "+f"((d)[0]), "+f"((d)[1]), "+f"((d)[2]), "+f"((d)[3])     \
                 : "r"((a)[0]), "r"((a)[1]), "r"((a)[2]), "r"((a)[3]),        \
                   "r"(b0_), "r"(b1_))

#define CP16(dst, src)                                                        \
    asm volatile("cp.async.cg.shared.global [%0], [%1], 16;" :: "r"(dst), "l"(src))
#define CP_COMMIT() asm volatile("cp.async.commit_group;" ::: "memory")
#define CP_WAIT1()  asm volatile("cp.async.wait_group 1;" ::: "memory")
#define GBAR(id)    asm volatile("bar.sync %0, 128;" :: "r"(id) : "memory")

__device__ __forceinline__ uint4 lds128(uint32_t a) {
    uint4 v;
    asm volatile("ld.shared.v4.b32 {%0,%1,%2,%3}, [%4];"
                 : "=r"(v.x), "=r"(v.y), "=r"(v.z), "=r"(v.w) : "r"(a));
    return v;
}

__device__ __forceinline__ float ex2(float x) {
    float y;
    asm("ex2.approx.ftz.f32 %0, %1;" : "=f"(y) : "f"(x));
    return y;
}
#define LOG2E 1.4426950408889634f
#define CVTPK(d, hi_, lo_)                                                    \
    asm("cvt.rn.satfinite.f16x2.f32 %0, %1, %2;" : "=r"(d) : "f"(hi_), "f"(lo_))

#define KOFF  0
#define VOFF  49152
#define QOFF  98304
#define SMEMSZ 114688
#define FSW(x) ((((x) & 1) << 2) | (((x) & 7) >> 1))

__global__ __launch_bounds__(256, 1) void attn_kernel(float* __restrict__ out)
{
    extern __shared__ __align__(16) uint8_t sm[];
    const int tid = threadIdx.x;
    const int warp = tid >> 5, lane = tid & 31;
    const int g = lane >> 2, r = lane & 3;
    const int gid = tid >> 7;
    const int wg_tid = tid & 127;
    const int wq = warp & 3;
    const int b = blockIdx.y;
    const int m0 = (int)(((unsigned)blockIdx.x * 7872u) / 73u);
    const int mw = wq * 16;

    const uint32_t sb = smem_u32(sm);
    const int fg = FSW(g);
    const uint32_t co0 = (uint32_t)(((((fg >> 2) ^ 0) << 2) | (r ^ (fg & 3))) * 16);
    const uint32_t co1 = (uint32_t)(((((fg >> 2) ^ 1) << 2) | (r ^ (fg & 3))) * 16);
    const uint32_t gco = (uint32_t)(g * 128);

    const int srow = wg_tid >> 1, hb = wg_tid & 1;
    const int fr = FSW(srow);
    const uint32_t kdst = sb + KOFF + srow * 128;
    const uint32_t vdst = sb + VOFF + srow * 128;
    const uint8_t* kg = (const uint8_t*)g_Kh + ((size_t)b * NN + srow) * 128;
    const uint8_t* vg = (const uint8_t*)g_Vh + ((size_t)(b * CH) + srow) * (NN * 2);

#pragma unroll
    for (int sdx = 0; sdx < 2; sdx++) {
        const int tt = gid + 2 * sdx;
        const uint32_t kd = kdst + tt * 8192;
        const uint32_t vd = vdst + tt * 8192;
        const uint8_t* kgs = kg + (size_t)tt * 8192;
        const uint8_t* vgs = vg + (size_t)tt * 128;
#pragma unroll
        for (int i = 0; i < 4; i++) {
            int c = hb * 4 + i;
            CP16(kd + (uint32_t)((c ^ fr) * 16), kgs + c * 16);
        }
#pragma unroll
        for (int i = 0; i < 4; i++) {
            int c = hb * 4 + i;
            CP16(vd + (uint32_t)((c ^ fr) * 16), vgs + c * 16);
        }
        CP_COMMIT();
    }

    {
        const int qrow = tid >> 1, h4 = tid & 1;
        const int fq = FSW(qrow);
        const uint8_t* qsrc = (const uint8_t*)g_Qh + ((size_t)b * NN + m0 + qrow) * 128;
#pragma unroll
        for (int j = 0; j < 4; j++) {
            int c = h4 * 4 + j;
            *reinterpret_cast<uint4*>(sm + QOFF + qrow * 128 + ((c ^ fq) * 16)) =
                *reinterpret_cast<const uint4*>(qsrc + c * 16);
        }
    }
    __syncthreads();

    uint32_t qa[2][4][4];
#pragma unroll
    for (int s = 0; s < 2; s++)
#pragma unroll
        for (int kp = 0; kp < 2; kp++)
#pragma unroll
            for (int h = 0; h < 2; h++) {
                uint4 v = lds128(sb + QOFF + (mw + s * 64 + h * 8 + g) * 128 + (kp ? co1 : co0));
                qa[s][2 * kp][h]         = v.x;
                qa[s][2 * kp + 1][h]     = v.y;
                qa[s][2 * kp][h + 2]     = v.z;
                qa[s][2 * kp + 1][h + 2] = v.w;
            }

    float oacc[2][8][4];
#pragma unroll
    for (int s = 0; s < 2; s++)
#pragma unroll
        for (int i = 0; i < 8; i++)
#pragma unroll
            for (int j = 0; j < 4; j++) oacc[s][i][j] = 0.f;
    float dacc[2][4] = {{0.f, 0.f, 0.f, 0.f}, {0.f, 0.f, 0.f, 0.f}};
    const uint32_t bones = 0x3C003C00u;

    int st = gid;
#pragma unroll 1
    for (int t = gid; t < 125; t += 2) {
        CP_WAIT1();
        GBAR(gid + 1);

        {
            int pst = st + 4; if (pst >= 6) pst -= 6;
            if (t + 4 < 125) {
                const int tt = t + 4;
                const uint32_t kd = kdst + pst * 8192;
                const uint32_t vd = vdst + pst * 8192;
                const uint8_t* kgs = kg + (size_t)tt * 8192;
                const uint8_t* vgs = vg + (size_t)tt * 128;
#pragma unroll
                for (int i = 0; i < 4; i++) {
                    int c = hb * 4 + i;
                    CP16(kd + (uint32_t)((c ^ fr) * 16), kgs + c * 16);
                }
#pragma unroll
                for (int i = 0; i < 4; i++) {
                    int c = hb * 4 + i;
                    CP16(vd + (uint32_t)((c ^ fr) * 16), vgs + c * 16);
                }
            }
            CP_COMMIT();
        }

        const uint32_t ksg = sb + KOFF + st * 8192 + gco;
        const uint32_t vsg = sb + VOFF + st * 8192 + gco;
        const uint32_t kb0 = ksg + co0, kb1 = ksg + co1;
        const uint32_t vb0 = vsg + co0, vb1 = vsg + co1;

#pragma unroll
        for (int kp = 0; kp < 2; kp++) {
            float s0[4][4], s1[4][4];
#pragma unroll
            for (int i = 0; i < 4; i++) {
                const int nb = 4 * kp + i;
#pragma unroll
                for (int j = 0; j < 4; j++) { s0[i][j] = 0.f; s1[i][j] = 0.f; }
                uint4 bv0 = lds128(kb0 + nb * 1024);
                MMA16(s0[i], qa[0][0], bv0.x, bv0.z);
                MMA16(s0[i], qa[0][1], bv0.y, bv0.w);
                MMA16(s1[i], qa[1][0], bv0.x, bv0.z);
                MMA16(s1[i], qa[1][1], bv0.y, bv0.w);
                uint4 bv1 = lds128(kb1 + nb * 1024);
                MMA16(s0[i], qa[0][2], bv1.x, bv1.z);
                MMA16(s0[i], qa[0][3], bv1.y, bv1.w);
                MMA16(s1[i], qa[1][2], bv1.x, bv1.z);
                MMA16(s1[i], qa[1][3], bv1.y, bv1.w);
            }

            uint32_t pa0[2][4], pa1[2][4];
#pragma unroll
            for (int j = 0; j < 2; j++) {
                float e00 = ex2(fmaf(s0[2 * j][0], LOG2E, -18.f));
                float e01 = ex2(fmaf(s0[2 * j][1], LOG2E, -18.f));
                float e02 = ex2(fmaf(s0[2 * j][2], LOG2E, -18.f));
                float e03 = ex2(fmaf(s0[2 * j][3], LOG2E, -18.f));
                float e10 = ex2(fmaf(s0[2 * j + 1][0], LOG2E, -18.f));
                float e11 = ex2(fmaf(s0[2 * j + 1][1], LOG2E, -18.f));
                float e12 = ex2(fmaf(s0[2 * j + 1][2], LOG2E, -18.f));
                float e13 = ex2(fmaf(s0[2 * j + 1][3], LOG2E, -18.f));
                CVTPK(pa0[j][0], e01, e00);
                CVTPK(pa0[j][1], e03, e02);
                CVTPK(pa0[j][2], e11, e10);
                CVTPK(pa0[j][3], e13, e12);
                float f00 = ex2(fmaf(s1[2 * j][0], LOG2E, -18.f));
                float f01 = ex2(fmaf(s1[2 * j][1], LOG2E, -18.f));
                float f02 = ex2(fmaf(s1[2 * j][2], LOG2E, -18.f));
                float f03 = ex2(fmaf(s1[2 * j][3], LOG2E, -18.f));
                float f10 = ex2(fmaf(s1[2 * j + 1][0], LOG2E, -18.f));
                float f11 = ex2(fmaf(s1[2 * j + 1][1], LOG2E, -18.f));
                float f12 = ex2(fmaf(s1[2 * j + 1][2], LOG2E, -18.f));
                float f13 = ex2(fmaf(s1[2 * j + 1][3], LOG2E, -18.f));
                CVTPK(pa1[j][0], f01, f00);
                CVTPK(pa1[j][1], f03, f02);
                CVTPK(pa1[j][2], f11, f10);
                CVTPK(pa1[j][3], f13, f12);
            }

            MMA16(dacc[0], pa0[0], bones, bones);
            MMA16(dacc[0], pa0[1], bones, bones);
            MMA16(dacc[1], pa1[0], bones, bones);
            MMA16(dacc[1], pa1[1], bones, bones);

            const uint32_t vbk = kp ? vb1 : vb0;
#pragma unroll
            for (int cb = 0; cb < 8; cb++) {
                uint4 bv = lds128(vbk + cb * 1024);
                MMA16(oacc[0][cb], pa0[0], bv.x, bv.z);
                MMA16(oacc[0][cb], pa0[1], bv.y, bv.w);
                MMA16(oacc[1][cb], pa1[0], bv.x, bv.z);
                MMA16(oacc[1][cb], pa1[1], bv.y, bv.w);
            }
        }

        st += 2; if (st >= 6) st -= 6;
    }

    __syncthreads();
    const uint32_t scr = sb + KOFF + (uint32_t)((wq * 32 + lane) * 69 * 4);
    if (gid == 1) {
#pragma unroll
        for (int s = 0; s < 2; s++) {
#pragma unroll
            for (int i = 0; i < 8; i++)
#pragma unroll
                for (int j = 0; j < 4; j++)
                    asm volatile("st.shared.f32 [%0], %1;"
                                 :: "r"(scr + (s * 34 + i * 4 + j) * 4), "f"(oacc[s][i][j]) : "memory");
            asm volatile("st.shared.f32 [%0], %1;" :: "r"(scr + (s * 34 + 32) * 4), "f"(dacc[s][0]) : "memory");
            asm volatile("st.shared.f32 [%0], %1;" :: "r"(scr + (s * 34 + 33) * 4), "f"(dacc[s][2]) : "memory");
        }
    }
    __syncthreads();
    if (gid == 0) {
#pragma unroll
        for (int s = 0; s < 2; s++) {
#pragma unroll
            for (int i = 0; i < 8; i++)
#pragma unroll
                for (int j = 0; j < 4; j++) {
                    float v;
                    asm volatile("ld.shared.f32 %0, [%1];" : "=f"(v) : "r"(scr + (s * 34 + i * 4 + j) * 4));
                    oacc[s][i][j] += v;
                }
            float v0, v1;
            asm volatile("ld.shared.f32 %0, [%1];" : "=f"(v0) : "r"(scr + (s * 34 + 32) * 4));
            asm volatile("ld.shared.f32 %0, [%1];" : "=f"(v1) : "r"(scr + (s * 34 + 33) * 4));
            const float den0 = dacc[s][0] + v0, den1 = dacc[s][2] + v1;
            const float i0 = 1.f / den0, i1 = 1.f / den1;

            const int m = m0 + mw + s * 64 + g;
#pragma unroll
            for (int cb = 0; cb < 8; cb++) {
                int c = cb * 8 + 2 * r;
                out[((size_t)b * CH + c    ) * NN + m]     = oacc[s][cb][0] * i0;
                out[((size_t)b * CH + c + 1) * NN + m]     = oacc[s][cb][1] * i0;
                out[((size_t)b * CH + c    ) * NN + m + 8] = oacc[s][cb][2] * i1;
                out[((size_t)b * CH + c + 1) * NN + m + 8] = oacc[s][cb][3] * i1;
            }
        }
    }
}

extern "C" void kernel_launch(void* const* d_in, const int* in_sizes, int n_in,
                              void* d_out, int out_size)
{
    const float* x  = (const float*)d_in[0];
    const float* qw = (const float*)d_in[1];
    const float* qb = (const float*)d_in[2];
    const float* kw = (const float*)d_in[3];
    const float* kb = (const float*)d_in[4];
    const float* vw = (const float*)d_in[5];
    const float* vb = (const float*)d_in[6];
    float* out = (float*)d_out;

    cudaFuncSetAttribute(attn_kernel, cudaFuncAttributeMaxDynamicSharedMemorySize, SMEMSZ);
    conv_kernel<<<dim3(63, 2, 3), 256>>>(x, qw, qb, kw, kb, vw, vb);
    attn_kernel<<<dim3(74, 2), 256, SMEMSZ>>>(out);
}

// round 16
// speedup vs baseline: 1.0381x; 1.0381x over previous
#include <cuda_runtime.h>
#include <cuda_fp16.h>
#include <cstdint>

#define BATCH 2
#define CH    64
#define DD    20
#define NN    8000
#define SK    68

// Projections in fp16. g_Q,g_K: [b][n][c] with channel-words permuted for LDS.128 frags.
// g_V: [b][c][n] with key-words permuted within each 64-block.
__device__ __align__(256) __half g_Qh[BATCH * NN * CH];
__device__ __align__(256) __half g_Kh[BATCH * NN * CH];
__device__ __align__(256) __half g_Vh[BATCH * NN * CH];

#define FMA2(d, a, b_) \
    asm("fma.rn.f32x2 %0, %1, %2, %0;" : "+l"(d) : "l"(a), "l"(b_))

// ---------------------------------------------------------------------------
// Conv kernel v3: v1 shape (128 threads, 64-n tiles) + double-buffered Ws/Xs
// (ONE barrier per k-chunk, gather overlaps compute), f32x2 inner loop,
// smem-transposed coalesced output.
// ---------------------------------------------------------------------------
__global__ __launch_bounds__(128) void conv_kernel(
    const float* __restrict__ x,
    const float* __restrict__ qw, const float* __restrict__ qb,
    const float* __restrict__ kw, const float* __restrict__ kbias,
    const float* __restrict__ vw, const float* __restrict__ vb)
{
    const int nt = blockIdx.x, b = blockIdx.y, cv = blockIdx.z;
    const float* Wp = (cv == 0) ? qw : ((cv == 1) ? kw : vw);
    const float* Bp = (cv == 0) ? qb : ((cv == 1) ? kbias : vb);
    const int n0 = nt * 64, tid = threadIdx.x;

    __shared__ float Ws[2][16][SK];
    __shared__ float Xs[2][16][SK];
    __shared__ __align__(16) __half Os[64][SK];   // [n][c] (q/k) or [c][n] (v)

    const int tn = (tid & 15) * 4;
    const int tc = (tid >> 4) * 8;

    uint64_t acc2[4][4];
#pragma unroll
    for (int ip = 0; ip < 4; ip++)
#pragma unroll
        for (int j = 0; j < 4; j++) acc2[ip][j] = 0ull;

    const int ks = tid >> 3;
    const int nb = (tid & 7) * 8;
    int pd[8], ph[8], pw[8];
#pragma unroll
    for (int j = 0; j < 8; j++) {
        int n = n0 + nb + j;
        pd[j] = n / 400;
        int rem = n - pd[j] * 400;
        ph[j] = rem / 20;
        pw[j] = rem - ph[j] * 20;
    }

    auto stage = [&](int k0, int bf) {
#pragma unroll
        for (int i = 0; i < 2; i++) {
            int idx4 = tid * 2 + i;
            int co = idx4 >> 2, k4 = (idx4 & 3) * 4;
            float4 wv = *reinterpret_cast<const float4*>(Wp + co * 192 + k0 + k4);
            Ws[bf][k4 + 0][co] = wv.x; Ws[bf][k4 + 1][co] = wv.y;
            Ws[bf][k4 + 2][co] = wv.z; Ws[bf][k4 + 3][co] = wv.w;
        }
        {
            int kk = k0 + ks;
            int ci = kk / 3;
            int dt = kk - ci * 3 - 1;
#pragma unroll
            for (int j = 0; j < 8; j++) {
                int d = pd[j], h = ph[j], w = pw[j];
                if (cv == 0) h += dt; else if (cv == 1) d += dt; else w += dt;
                unsigned cd = (cv == 0) ? (unsigned)h : ((cv == 1) ? (unsigned)d : (unsigned)w);
                float val = 0.f;
                if (cd < 20u)
                    val = x[((b * CH + ci) * DD + d) * 400 + h * 20 + w];
                Xs[bf][ks][nb + j] = val;
            }
        }
    };

    stage(0, 0);
    __syncthreads();

    for (int c = 0; c < 12; c++) {
        if (c + 1 < 12) stage((c + 1) * 16, (c + 1) & 1);   // overlaps compute below
        const int bf = c & 1;
#pragma unroll
        for (int kk = 0; kk < 16; kk++) {
            float4 xr = *reinterpret_cast<const float4*>(&Xs[bf][kk][tn]);
            const uint64_t* wp = reinterpret_cast<const uint64_t*>(&Ws[bf][kk][tc]);
            uint64_t w2[4];
            w2[0] = wp[0]; w2[1] = wp[1]; w2[2] = wp[2]; w2[3] = wp[3];
            uint64_t xb[4];
            asm("mov.b64 %0, {%1,%1};" : "=l"(xb[0]) : "f"(xr.x));
            asm("mov.b64 %0, {%1,%1};" : "=l"(xb[1]) : "f"(xr.y));
            asm("mov.b64 %0, {%1,%1};" : "=l"(xb[2]) : "f"(xr.z));
            asm("mov.b64 %0, {%1,%1};" : "=l"(xb[3]) : "f"(xr.w));
#pragma unroll
            for (int ip = 0; ip < 4; ip++) {
                FMA2(acc2[ip][0], w2[ip], xb[0]);
                FMA2(acc2[ip][1], w2[ip], xb[1]);
                FMA2(acc2[ip][2], w2[ip], xb[2]);
                FMA2(acc2[ip][3], w2[ip], xb[3]);
            }
        }
        __syncthreads();   // staged chunk c+1 visible; buf (c&1) free for restage at c+2
    }

    // ---- stage results in smem (fp16), natural layout ----
#pragma unroll
    for (int ip = 0; ip < 4; ip++) {
        float lo[4], hi[4];
#pragma unroll
        for (int j = 0; j < 4; j++)
            asm("mov.b64 {%0,%1}, %2;" : "=f"(lo[j]), "=f"(hi[j]) : "l"(acc2[ip][j]));
#pragma unroll
        for (int half = 0; half < 2; half++) {
            const int co = tc + 2 * ip + half;
            const float bias = Bp[co];
#pragma unroll
            for (int j = 0; j < 4; j++) {
                const int nl = tn + j;
                const __half hv = __float2half_rn((half ? hi[j] : lo[j]) + bias);
                if (cv == 2) Os[co][nl] = hv;
                else         Os[nl][co] = hv;
            }
        }
    }
    __syncthreads();

    // ---- coalesced output: gather 16 permuted words per thread, 4x STG.128 ----
    {
        const int R = tid >> 1, h4 = tid & 1;
        const uint32_t* Osw = reinterpret_cast<const uint32_t*>(&Os[R][0]);
        __half* dst;
        if (cv == 2) dst = g_Vh + ((size_t)(b * CH + R)) * NN + n0;
        else         dst = (cv ? g_Kh : g_Qh) + ((size_t)(b * NN + n0 + R)) * CH;
        uint32_t wbuf[16];
#pragma unroll
        for (int idx = 0; idx < 16; idx++) {
            const int p = h4 * 16 + idx;
            const int k16 = ((p >> 4) << 1) | (p & 1);
            const int jj = (((p >> 1) & 1) << 2) | ((p >> 2) & 3);
            wbuf[idx] = Osw[k16 * 8 + jj];
        }
        uint4* d4 = reinterpret_cast<uint4*>(dst) + h4 * 4;
#pragma unroll
        for (int c = 0; c < 4; c++)
            d4[c] = make_uint4(wbuf[4 * c], wbuf[4 * c + 1], wbuf[4 * c + 2], wbuf[4 * c + 3]);
    }
}

// ---------------------------------------------------------------------------
// Attention kernel: m32 per warp, 256 threads, 1 CTA/SM, two key-split groups,
// 6-stage ring, one barrier per tile, kp-split body. den via FADD (fma pipe)
// instead of ones-MMA — relieves the tensor pipe (busiest at 55%).
// ---------------------------------------------------------------------------
__device__ __forceinline__ uint32_t smem_u32(const void* p) {
    uint32_t a;
    asm("{ .reg .u64 t; cvta.to.shared.u64 t, %1; cvt.u32.u64 %0, t; }" : "=r"(a) : "l"(p));
    return a;
}

#define MMA16(d, a, b0_, b1_)                                                 \
    asm volatile("mma.sync.aligned.m16n8k16.row.col.f32.f16.f16.f32 "         \
                 "{%0,%1,%2,%3},{%4,%5,%6,%7},{%8,%9},{%0,%1,%2,%3};"         \
                 : "+f"((d)[0]), "+f"((d)[1]), "+f"((d)[2]), "+f"((d)[3])     \
                 : "r"((a)[0]), "r"((a)[1]), "r"((a)[2]), "r"((a)[3]),        \
                   "r"(b0_), "r"(b1_))

#define CP16(dst, src)                                                        \
    asm volatile("cp.async.cg.shared.global [%0], [%1], 16;" :: "r"(dst), "l"(src))
#define CP_COMMIT() asm volatile("cp.async.commit_group;" ::: "memory")
#define CP_WAIT1()  asm volatile("cp.async.wait_group 1;" ::: "memory")
#define GBAR(id)    asm volatile("bar.sync %0, 128;" :: "r"(id) : "memory")

__device__ __forceinline__ uint4 lds128(uint32_t a) {
    uint4 v;
    asm volatile("ld.shared.v4.b32 {%0,%1,%2,%3}, [%4];"
                 : "=r"(v.x), "=r"(v.y), "=r"(v.z), "=r"(v.w) : "r"(a));
    return v;
}

__device__ __forceinline__ float ex2(float x) {
    float y;
    asm("ex2.approx.ftz.f32 %0, %1;" : "=f"(y) : "f"(x));
    return y;
}
#define LOG2E 1.4426950408889634f
#define CVTPK(d, hi_, lo_)                                                    \
    asm("cvt.rn.satfinite.f16x2.f32 %0, %1, %2;" : "=r"(d) : "f"(hi_), "f"(lo_))

#define KOFF  0
#define VOFF  49152
#define QOFF  98304
#define SMEMSZ 114688
#define FSW(x) ((((x) & 1) << 2) | (((x) & 7) >> 1))

__global__ __launch_bounds__(256, 1) void attn_kernel(float* __restrict__ out)
{
    extern __shared__ __align__(16) uint8_t sm[];
    const int tid = threadIdx.x;
    const int warp = tid >> 5, lane = tid & 31;
    const int g = lane >> 2, r = lane & 3;
    const int gid = tid >> 7;
    const int wg_tid = tid & 127;
    const int wq = warp & 3;
    const int b = blockIdx.y;
    const int m0 = (int)(((unsigned)blockIdx.x * 7872u) / 73u);
    const int mw = wq * 16;

    const uint32_t sb = smem_u32(sm);
    const int fg = FSW(g);
    const uint32_t co0 = (uint32_t)(((((fg >> 2) ^ 0) << 2) | (r ^ (fg & 3))) * 16);
    const uint32_t co1 = (uint32_t)(((((fg >> 2) ^ 1) << 2) | (r ^ (fg & 3))) * 16);
    const uint32_t gco = (uint32_t)(g * 128);

    const int srow = wg_tid >> 1, hb = wg_tid & 1;
    const int fr = FSW(srow);
    const uint32_t kdst = sb + KOFF + srow * 128;
    const uint32_t vdst = sb + VOFF + srow * 128;
    const uint8_t* kg = (const uint8_t*)g_Kh + ((size_t)b * NN + srow) * 128;
    const uint8_t* vg = (const uint8_t*)g_Vh + ((size_t)(b * CH) + srow) * (NN * 2);

#pragma unroll
    for (int sdx = 0; sdx < 2; sdx++) {
        const int tt = gid + 2 * sdx;
        const uint32_t kd = kdst + tt * 8192;
        const uint32_t vd = vdst + tt * 8192;
        const uint8_t* kgs = kg + (size_t)tt * 8192;
        const uint8_t* vgs = vg + (size_t)tt * 128;
#pragma unroll
        for (int i = 0; i < 4; i++) {
            int c = hb * 4 + i;
            CP16(kd + (uint32_t)((c ^ fr) * 16), kgs + c * 16);
        }
#pragma unroll
        for (int i = 0; i < 4; i++) {
            int c = hb * 4 + i;
            CP16(vd + (uint32_t)((c ^ fr) * 16), vgs + c * 16);
        }
        CP_COMMIT();
    }

    {
        const int qrow = tid >> 1, h4 = tid & 1;
        const int fq = FSW(qrow);
        const uint8_t* qsrc = (const uint8_t*)g_Qh + ((size_t)b * NN + m0 + qrow) * 128;
#pragma unroll
        for (int j = 0; j < 4; j++) {
            int c = h4 * 4 + j;
            *reinterpret_cast<uint4*>(sm + QOFF + qrow * 128 + ((c ^ fq) * 16)) =
                *reinterpret_cast<const uint4*>(qsrc + c * 16);
        }
    }
    __syncthreads();

    uint32_t qa[2][4][4];
#pragma unroll
    for (int s = 0; s < 2; s++)
#pragma unroll
        for (int kp = 0; kp < 2; kp++)
#pragma unroll
            for (int h = 0; h < 2; h++) {
                uint4 v = lds128(sb + QOFF + (mw + s * 64 + h * 8 + g) * 128 + (kp ? co1 : co0));
                qa[s][2 * kp][h]         = v.x;
                qa[s][2 * kp + 1][h]     = v.y;
                qa[s][2 * kp][h + 2]     = v.z;
                qa[s][2 * kp + 1][h + 2] = v.w;
            }

    float oacc[2][8][4];
#pragma unroll
    for (int s = 0; s < 2; s++)
#pragma unroll
        for (int i = 0; i < 8; i++)
#pragma unroll
            for (int j = 0; j < 4; j++) oacc[s][i][j] = 0.f;
    float den[2][2] = {{0.f, 0.f}, {0.f, 0.f}};   // [strip][row half], FADD accumulation

    int st = gid;
#pragma unroll 1
    for (int t = gid; t < 125; t += 2) {
        CP_WAIT1();
        GBAR(gid + 1);

        {
            int pst = st + 4; if (pst >= 6) pst -= 6;
            if (t + 4 < 125) {
                const int tt = t + 4;
                const uint32_t kd = kdst + pst * 8192;
                const uint32_t vd = vdst + pst * 8192;
                const uint8_t* kgs = kg + (size_t)tt * 8192;
                const uint8_t* vgs = vg + (size_t)tt * 128;
#pragma unroll
                for (int i = 0; i < 4; i++) {
                    int c = hb * 4 + i;
                    CP16(kd + (uint32_t)((c ^ fr) * 16), kgs + c * 16);
                }
#pragma unroll
                for (int i = 0; i < 4; i++) {
                    int c = hb * 4 + i;
                    CP16(vd + (uint32_t)((c ^ fr) * 16), vgs + c * 16);
                }
            }
            CP_COMMIT();
        }

        const uint32_t ksg = sb + KOFF + st * 8192 + gco;
        const uint32_t vsg = sb + VOFF + st * 8192 + gco;
        const uint32_t kb0 = ksg + co0, kb1 = ksg + co1;
        const uint32_t vb0 = vsg + co0, vb1 = vsg + co1;

#pragma unroll
        for (int kp = 0; kp < 2; kp++) {
            float s0[4][4], s1[4][4];
#pragma unroll
            for (int i = 0; i < 4; i++) {
                const int nb = 4 * kp + i;
#pragma unroll
                for (int j = 0; j < 4; j++) { s0[i][j] = 0.f; s1[i][j] = 0.f; }
                uint4 bv0 = lds128(kb0 + nb * 1024);
                MMA16(s0[i], qa[0][0], bv0.x, bv0.z);
                MMA16(s0[i], qa[0][1], bv0.y, bv0.w);
                MMA16(s1[i], qa[1][0], bv0.x, bv0.z);
                MMA16(s1[i], qa[1][1], bv0.y, bv0.w);
                uint4 bv1 = lds128(kb1 + nb * 1024);
                MMA16(s0[i], qa[0][2], bv1.x, bv1.z);
                MMA16(s0[i], qa[0][3], bv1.y, bv1.w);
                MMA16(s1[i], qa[1][2], bv1.x, bv1.z);
                MMA16(s1[i], qa[1][3], bv1.y, bv1.w);
            }

            uint32_t pa0[2][4], pa1[2][4];
#pragma unroll
            for (int j = 0; j < 2; j++) {
                float e00 = ex2(fmaf(s0[2 * j][0], LOG2E, -18.f));
                float e01 = ex2(fmaf(s0[2 * j][1], LOG2E, -18.f));
                float e02 = ex2(fmaf(s0[2 * j][2], LOG2E, -18.f));
                float e03 = ex2(fmaf(s0[2 * j][3], LOG2E, -18.f));
                float e10 = ex2(fmaf(s0[2 * j + 1][0], LOG2E, -18.f));
                float e11 = ex2(fmaf(s0[2 * j + 1][1], LOG2E, -18.f));
                float e12 = ex2(fmaf(s0[2 * j + 1][2], LOG2E, -18.f));
                float e13 = ex2(fmaf(s0[2 * j + 1][3], LOG2E, -18.f));
                den[0][0] += (e00 + e01) + (e10 + e11);
                den[0][1] += (e02 + e03) + (e12 + e13);
                CVTPK(pa0[j][0], e01, e00);
                CVTPK(pa0[j][1], e03, e02);
                CVTPK(pa0[j][2], e11, e10);
                CVTPK(pa0[j][3], e13, e12);
                float f00 = ex2(fmaf(s1[2 * j][0], LOG2E, -18.f));
                float f01 = ex2(fmaf(s1[2 * j][1], LOG2E, -18.f));
                float f02 = ex2(fmaf(s1[2 * j][2], LOG2E, -18.f));
                float f03 = ex2(fmaf(s1[2 * j][3], LOG2E, -18.f));
                float f10 = ex2(fmaf(s1[2 * j + 1][0], LOG2E, -18.f));
                float f11 = ex2(fmaf(s1[2 * j + 1][1], LOG2E, -18.f));
                float f12 = ex2(fmaf(s1[2 * j + 1][2], LOG2E, -18.f));
                float f13 = ex2(fmaf(s1[2 * j + 1][3], LOG2E, -18.f));
                den[1][0] += (f00 + f01) + (f10 + f11);
                den[1][1] += (f02 + f03) + (f12 + f13);
                CVTPK(pa1[j][0], f01, f00);
                CVTPK(pa1[j][1], f03, f02);
                CVTPK(pa1[j][2], f11, f10);
                CVTPK(pa1[j][3], f13, f12);
            }

            const uint32_t vbk = kp ? vb1 : vb0;
#pragma unroll
            for (int cb = 0; cb < 8; cb++) {
                uint4 bv = lds128(vbk + cb * 1024);
                MMA16(oacc[0][cb], pa0[0], bv.x, bv.z);
                MMA16(oacc[0][cb], pa0[1], bv.y, bv.w);
                MMA16(oacc[1][cb], pa1[0], bv.x, bv.z);
                MMA16(oacc[1][cb], pa1[1], bv.y, bv.w);
            }
        }

        st += 2; if (st >= 6) st -= 6;
    }

    // ---- reduce den over the 4 lanes sharing each m row ----
#pragma unroll
    for (int s = 0; s < 2; s++)
#pragma unroll
        for (int h = 0; h < 2; h++) {
            den[s][h] += __shfl_xor_sync(0xffffffffu, den[s][h], 1);
            den[s][h] += __shfl_xor_sync(0xffffffffu, den[s][h], 2);
        }

    // ---- merge group B partials into group A via smem (reuse K+V rings) ----
    __syncthreads();
    const uint32_t scr = sb + KOFF + (uint32_t)((wq * 32 + lane) * 69 * 4);
    if (gid == 1) {
#pragma unroll
        for (int s = 0; s < 2; s++) {
#pragma unroll
            for (int i = 0; i < 8; i++)
#pragma unroll
                for (int j = 0; j < 4; j++)
                    asm volatile("st.shared.f32 [%0], %1;"
                                 :: "r"(scr + (s * 34 + i * 4 + j) * 4), "f"(oacc[s][i][j]) : "memory");
            asm volatile("st.shared.f32 [%0], %1;" :: "r"(scr + (s * 34 + 32) * 4), "f"(den[s][0]) : "memory");
            asm volatile("st.shared.f32 [%0], %1;" :: "r"(scr + (s * 34 + 33) * 4), "f"(den[s][1]) : "memory");
        }
    }
    __syncthreads();
    if (gid == 0) {
#pragma unroll
        for (int s = 0; s < 2; s++) {
#pragma unroll
            for (int i = 0; i < 8; i++)
#pragma unroll
                for (int j = 0; j < 4; j++) {
                    float v;
                    asm volatile("ld.shared.f32 %0, [%1];" : "=f"(v) : "r"(scr + (s * 34 + i * 4 + j) * 4));
                    oacc[s][i][j] += v;
                }
            float v0, v1;
            asm volatile("ld.shared.f32 %0, [%1];" : "=f"(v0) : "r"(scr + (s * 34 + 32) * 4));
            asm volatile("ld.shared.f32 %0, [%1];" : "=f"(v1) : "r"(scr + (s * 34 + 33) * 4));
            const float den0 = den[s][0] + v0, den1 = den[s][1] + v1;
            const float i0 = 1.f / den0, i1 = 1.f / den1;

            const int m = m0 + mw + s * 64 + g;
#pragma unroll
            for (int cb = 0; cb < 8; cb++) {
                int c = cb * 8 + 2 * r;
                out[((size_t)b * CH + c    ) * NN + m]     = oacc[s][cb][0] * i0;
                out[((size_t)b * CH + c + 1) * NN + m]     = oacc[s][cb][1] * i0;
                out[((size_t)b * CH + c    ) * NN + m + 8] = oacc[s][cb][2] * i1;
                out[((size_t)b * CH + c + 1) * NN + m + 8] = oacc[s][cb][3] * i1;
            }
        }
    }
}

extern "C" void kernel_launch(void* const* d_in, const int* in_sizes, int n_in,
                              void* d_out, int out_size)
{
    const float* x  = (const float*)d_in[0];
    const float* qw = (const float*)d_in[1];
    const float* qb = (const float*)d_in[2];
    const float* kw = (const float*)d_in[3];
    const float* kb = (const float*)d_in[4];
    const float* vw = (const float*)d_in[5];
    const float* vb = (const float*)d_in[6];
    float* out = (float*)d_out;

    cudaFuncSetAttribute(attn_kernel, cudaFuncAttributeMaxDynamicSharedMemorySize, SMEMSZ);
    conv_kernel<<<dim3(125, 2, 3), 128>>>(x, qw, qb, kw, kb, vw, vb);
    attn_kernel<<<dim3(74, 2), 256, SMEMSZ>>>(out);
}